// round 1
// baseline (speedup 1.0000x reference)
#include <cuda_runtime.h>
#include <math.h>

// SpectralAngleLoss: B=8192 rows, N=256 peaks/row, 2000 bins.
// Per-row smem histograms -> cosine -> arccos -> deterministic mean.

#define N_PEAKS   256
#define NUM_BINS  2000
#define MAX_ROWS  8192
#define THREADS   256

__device__ float g_partials[MAX_ROWS];

__global__ __launch_bounds__(THREADS)
void sal_row_kernel(const float* __restrict__ pred_mz,
                    const float* __restrict__ pred_int,
                    const float* __restrict__ targ_mz,
                    const float* __restrict__ targ_int,
                    const float* __restrict__ targ_mask)
{
    __shared__ float ph[NUM_BINS];   // pred histogram
    __shared__ float th[NUM_BINS];   // target histogram
    __shared__ float red[3][THREADS / 32];

    const int row = blockIdx.x;
    const int tid = threadIdx.x;

    // Zero histograms with float4 stores (2000 floats = 500 float4 per array)
    {
        float4 z = make_float4(0.f, 0.f, 0.f, 0.f);
        float4* ph4 = reinterpret_cast<float4*>(ph);
        float4* th4 = reinterpret_cast<float4*>(th);
        #pragma unroll
        for (int i = tid; i < NUM_BINS / 4; i += THREADS) {
            ph4[i] = z;
            th4[i] = z;
        }
    }
    __syncthreads();

    // Scatter: one peak per thread per spectrum, coalesced loads.
    const int idx = row * N_PEAKS + tid;
    {
        float mzp = pred_mz[idx];
        float ip  = pred_int[idx];
        int bp = (int)(mzp * 2000.0f);           // trunc-toward-zero == astype(int32)
        bp = min(max(bp, 0), NUM_BINS - 1);
        atomicAdd(&ph[bp], ip);

        float mzt = targ_mz[idx];
        float it  = targ_int[idx] * targ_mask[idx];
        int bt = (int)(mzt * 2000.0f);
        bt = min(max(bt, 0), NUM_BINS - 1);
        atomicAdd(&th[bt], it);
    }
    __syncthreads();

    // Strided scan over bins: dot, |p|^2, |t|^2
    float dot = 0.f, pn = 0.f, tn = 0.f;
    #pragma unroll
    for (int i = tid; i < NUM_BINS; i += THREADS) {
        float p = ph[i];
        float t = th[i];
        dot = fmaf(p, t, dot);
        pn  = fmaf(p, p, pn);
        tn  = fmaf(t, t, tn);
    }

    // Warp reduce
    #pragma unroll
    for (int o = 16; o > 0; o >>= 1) {
        dot += __shfl_xor_sync(0xFFFFFFFFu, dot, o);
        pn  += __shfl_xor_sync(0xFFFFFFFFu, pn,  o);
        tn  += __shfl_xor_sync(0xFFFFFFFFu, tn,  o);
    }
    if ((tid & 31) == 0) {
        int w = tid >> 5;
        red[0][w] = dot;
        red[1][w] = pn;
        red[2][w] = tn;
    }
    __syncthreads();

    if (tid == 0) {
        float d = 0.f, a = 0.f, b = 0.f;
        #pragma unroll
        for (int w = 0; w < THREADS / 32; w++) {
            d += red[0][w];
            a += red[1][w];
            b += red[2][w];
        }
        const float eps = 1e-8f;
        float denom = fmaxf(sqrtf(a), eps) * fmaxf(sqrtf(b), eps);
        float c = d / denom;
        c = fminf(fmaxf(c, -1.0f), 1.0f);
        g_partials[row] = acosf(c);
    }
}

__global__ __launch_bounds__(1024)
void sal_reduce_kernel(float* __restrict__ out, int rows)
{
    __shared__ float s[1024];
    int tid = threadIdx.x;
    float v = 0.f;
    for (int i = tid; i < rows; i += 1024)
        v += g_partials[i];
    s[tid] = v;
    __syncthreads();
    #pragma unroll
    for (int o = 512; o > 0; o >>= 1) {
        if (tid < o) s[tid] += s[tid + o];
        __syncthreads();
    }
    if (tid == 0)
        out[0] = s[0] / ((float)rows * 3.14159265358979323846f);  // WEIGHT=1
}

extern "C" void kernel_launch(void* const* d_in, const int* in_sizes, int n_in,
                              void* d_out, int out_size)
{
    const float* pred_mz   = (const float*)d_in[0];
    const float* pred_int  = (const float*)d_in[1];
    const float* targ_mz   = (const float*)d_in[2];
    const float* targ_int  = (const float*)d_in[3];
    const float* targ_mask = (const float*)d_in[4];
    float* out = (float*)d_out;

    int rows = in_sizes[0] / N_PEAKS;
    if (rows > MAX_ROWS) rows = MAX_ROWS;

    sal_row_kernel<<<rows, THREADS>>>(pred_mz, pred_int, targ_mz, targ_int, targ_mask);
    sal_reduce_kernel<<<1, 1024>>>(out, rows);
}